// round 12
// baseline (speedup 1.0000x reference)
#include <cuda_runtime.h>
#include <cuda_bf16.h>

// LSTM: B=4096, T=200, IN=2, H=64, gates=256 (i,f,g,o torch order)
//
// R10 design (from R10 ncu: fma 54.7 / L1 53.4 / issue 45.7 -> no pipe bound;
// gap attributed to per-step double-barrier convoys + gsm gate round-trip):
//  * lane-pair gate ownership: half0 lane computes (i_j, f_j), half1 lane
//    (g_j, o_j) for the same j; exchange pre-activations via shfl.xor(1).
//    -> no gate smem, no barrier between gates and activations.
//  * h double-buffered -> single barrier per step.
//  * q-groups (128 thr, 14 batch rows) are fully independent -> named
//    128-thread barrier instead of CTA-wide syncthreads.
// AI unchanged: 1 LDS.128 feeds 4 FFMA2; 2 gate rows/thread, 128 weight regs.

#define B_TOT   4096
#define T_LEN   200
#define H_DIM   64
#define BR      28            // batch rows per CTA
#define QROWS   14            // rows per q-group
#define NTHR    256

// smem float offsets: h double buffer | x
#define H_SZ     (BR * H_DIM)             // 1792 floats per buffer
#define XS_OFF   (2 * H_SZ)               // 3584
#define XS_SZ    (T_LEN * BR * 2)         // 11200 floats
#define SMEM_FLOATS (XS_OFF + XS_SZ)
#define SMEM_BYTES  (SMEM_FLOATS * 4)

__device__ __forceinline__ unsigned long long pack2(float a, float b) {
    unsigned long long r;
    asm("mov.b64 %0, {%1, %2};" : "=l"(r) : "f"(a), "f"(b));
    return r;
}
__device__ __forceinline__ void unpack2(unsigned long long v, float& a, float& b) {
    asm("mov.b64 {%0, %1}, %2;" : "=f"(a), "=f"(b) : "l"(v));
}
__device__ __forceinline__ unsigned long long fma2(unsigned long long a,
                                                   unsigned long long b,
                                                   unsigned long long c) {
    unsigned long long d;
    asm("fma.rn.f32x2 %0, %1, %2, %3;" : "=l"(d) : "l"(a), "l"(b), "l"(c));
    return d;
}
__device__ __forceinline__ unsigned long long add2(unsigned long long a,
                                                   unsigned long long b) {
    unsigned long long d;
    asm("add.rn.f32x2 %0, %1, %2;" : "=l"(d) : "l"(a), "l"(b));
    return d;
}

__device__ __forceinline__ float ex2f(float x) {
    float r; asm("ex2.approx.f32 %0, %1;" : "=f"(r) : "f"(x)); return r;
}
__device__ __forceinline__ float rcpf(float x) {
    float r; asm("rcp.approx.f32 %0, %1;" : "=f"(r) : "f"(x)); return r;
}
__device__ __forceinline__ float sigf(float x) {
    float e = ex2f(-1.4426950408889634f * x);
    return rcpf(1.0f + e);
}
__device__ __forceinline__ float tanhf_(float x) {
    float e = ex2f(-2.8853900817779268f * x);
    return fmaf(2.0f, rcpf(1.0f + e), -1.0f);
}

__global__ __launch_bounds__(NTHR, 1)
void lstm_kernel(const float* __restrict__ x,
                 const float* __restrict__ W_ih,
                 const float* __restrict__ W_hh,
                 const float* __restrict__ b_ih,
                 const float* __restrict__ b_hh,
                 const float* __restrict__ W_fc,
                 const float* __restrict__ b_fc,
                 float* __restrict__ out) {
    extern __shared__ float sm[];
    float*  hbuf = sm;                    // [2][28][64]
    float2* xsf  = (float2*)(sm + XS_OFF); // [200][28]

    const int tid  = threadIdx.x;
    const int half = tid & 1;             // 0: (i,f)   1: (g,o)
    const int j    = (tid >> 1) & 63;     // h column owned
    const int q    = tid >> 7;            // batch-row group 0/1
    const int gA   = half ? (j + 128) : j;          // g : i
    const int gB   = half ? (j + 192) : (j + 64);   // o : f
    const int b0   = q * QROWS;
    const int base = blockIdx.x * BR;

    // ---- W_hh rows for 2 gates, k-packed f32x2 (128 regs) ----
    unsigned long long wa[H_DIM / 2], wb[H_DIM / 2];
    {
        const float2* wrA = (const float2*)(W_hh + gA * H_DIM);
        const float2* wrB = (const float2*)(W_hh + gB * H_DIM);
        #pragma unroll
        for (int m = 0; m < H_DIM / 2; m++) {
            float2 a = wrA[m]; wa[m] = pack2(a.x, a.y);
            float2 b = wrB[m]; wb[m] = pack2(b.x, b.y);
        }
    }
    const float xA0 = W_ih[gA * 2 + 0], xA1 = W_ih[gA * 2 + 1];
    const float xB0 = W_ih[gB * 2 + 0], xB1 = W_ih[gB * 2 + 1];
    const float biasA = b_ih[gA] + b_hh[gA];
    const float biasB = b_ih[gB] + b_hh[gB];
    const float bfc = b_fc[0];

    // ---- zero h buffer 0 ----
    for (int i = tid; i < H_SZ; i += NTHR) hbuf[i] = 0.0f;

    // ---- stage x: [t][b] -> float2(x0,x1) ----
    for (int id = tid; id < T_LEN * BR; id += NTHR) {
        int t = id / BR;
        int b = id - t * BR;
        int gb = base + b;
        float2 v = make_float2(0.0f, 0.0f);
        if (gb < B_TOT) v = *(const float2*)(x + gb * (T_LEN * 2) + 2 * t);
        xsf[t * BR + b] = v;
    }

    float c_state[7];
    #pragma unroll
    for (int r = 0; r < 7; r++) c_state[r] = 0.0f;

    const int own_lo = half ? 7 : 0;  // bb range this lane does phase 2 for
    __syncthreads();

    int rd = 0;
    for (int t = 0; t < T_LEN; t++) {
        const float*  hr_base = hbuf + rd * H_SZ;
        float*        hw_base = hbuf + (1 - rd) * H_SZ;
        const float2* xrow    = xsf + t * BR;

        #pragma unroll
        for (int bb = 0; bb < QROWS; bb++) {
            const int b = b0 + bb;
            const ulonglong2* hr = (const ulonglong2*)(hr_base + b * H_DIM);
            unsigned long long aA0 = pack2(0.0f, 0.0f);
            unsigned long long aA1 = aA0, aB0 = aA0, aB1 = aA0;
            #pragma unroll
            for (int m = 0; m < H_DIM / 4; m++) {
                ulonglong2 hv = hr[m];  // h[4m..4m+3] as two f32x2
                aA0 = fma2(hv.x, wa[2 * m + 0], aA0);
                aA1 = fma2(hv.y, wa[2 * m + 1], aA1);
                aB0 = fma2(hv.x, wb[2 * m + 0], aB0);
                aB1 = fma2(hv.y, wb[2 * m + 1], aB1);
            }
            float2 xv = xrow[b];
            float lA, hA, lB, hB;
            unpack2(add2(aA0, aA1), lA, hA);
            unpack2(add2(aB0, aB1), lB, hB);
            float gvA = biasA + xA0 * xv.x + xA1 * xv.y + (lA + hA);
            float gvB = biasB + xB0 * xv.x + xB1 * xv.y + (lB + hB);

            // exchange with partner lane (same j, other gate pair)
            float exA = __shfl_xor_sync(0xffffffffu, gvA, 1);
            float exB = __shfl_xor_sync(0xffffffffu, gvB, 1);

            if (bb >= own_lo && bb < own_lo + 7) {
                float gi = half ? exA : gvA;
                float gf = half ? exB : gvB;
                float gg = half ? gvA : exA;
                float go = half ? gvB : exB;
                int ci = bb - own_lo;
                float i_ = sigf(gi);
                float f_ = sigf(gf);
                float g_ = tanhf_(gg);
                float o_ = sigf(go);
                float c = f_ * c_state[ci] + i_ * g_;
                c_state[ci] = c;
                hw_base[b * H_DIM + j] = o_ * tanhf_(c);
            }
        }

        // sync only this q-group (4 warps, 128 threads)
        asm volatile("bar.sync %0, %1;" :: "r"(q + 1), "r"(128) : "memory");
        rd ^= 1;
    }

    // ---- final projection: out[b] = dot(h_last, W_fc) + b_fc ----
    __syncthreads();                       // join both q-groups
    if (tid < H_DIM) sm[XS_OFF + tid] = W_fc[tid];  // xs no longer needed
    __syncthreads();
    if (tid < BR) {
        int gb = base + tid;
        if (gb < B_TOT) {
            const float* hl = hbuf + rd * H_SZ + tid * H_DIM;
            float acc = 0.0f;
            #pragma unroll
            for (int jj = 0; jj < H_DIM; jj++)
                acc += hl[jj] * sm[XS_OFF + jj];
            out[gb] = acc + bfc;
        }
    }
}

extern "C" void kernel_launch(void* const* d_in, const int* in_sizes, int n_in,
                              void* d_out, int out_size) {
    const float* x    = (const float*)d_in[0];
    const float* W_ih = (const float*)d_in[1];
    const float* W_hh = (const float*)d_in[2];
    const float* b_ih = (const float*)d_in[3];
    const float* b_hh = (const float*)d_in[4];
    const float* W_fc = (const float*)d_in[5];
    const float* b_fc = (const float*)d_in[6];
    float* out = (float*)d_out;

    cudaFuncSetAttribute(lstm_kernel,
                         cudaFuncAttributeMaxDynamicSharedMemorySize,
                         SMEM_BYTES);

    int grid = (B_TOT + BR - 1) / BR;  // 147
    lstm_kernel<<<grid, NTHR, SMEM_BYTES>>>(x, W_ih, W_hh, b_ih, b_hh,
                                            W_fc, b_fc, out);
}

// round 16
// speedup vs baseline: 1.0403x; 1.0403x over previous
#include <cuda_runtime.h>
#include <cuda_bf16.h>

// LSTM: B=4096, T=200, IN=2, H=64, gates=256 (i,f,g,o torch order)
//
// R12 design. Post-mortems:
//  R3 (955us): L1 78.5% bound (1 LDS.128 per 2 FFMA2).
//  R4 (754us): AI doubled (4 FFMA2/LDS.128). fma 54.7 = its floor; remaining
//              time = phase2 + barriers running SERIALLY after phase1.
//  R10 (990us REGRESS): shfl/divergent phase2 poisoned the FMA stream.
// Fix: keep R4's dense ph1/ph2 bodies and gsm round-trip EXACTLY, but
// stagger the two batch halves so ph1(half X) overlaps ph2(other half,
// prev interval) on the same SMSP. Same 2 barriers/step; every gsm/h
// dependency crosses exactly one barrier (audited).
//   interval1: s0 warps ph1(rows 0-13, t)   | s1 warps ph2(rows 14-27, t-1)
//   interval2: s1 warps ph1(rows 14-27, t)  | s0 warps ph2(rows 0-13, t)

#define B_TOT   4096
#define T_LEN   200
#define H_DIM   64
#define G_DIM   256           // 4*H
#define BR      28            // batch rows per CTA
#define HROWS   14            // rows per half
#define NTHR    256

// smem float offsets: hsm | gsm | xs
#define HS_OFF   0
#define HS_SZ    (BR * H_DIM)             // 1792 floats
#define GS_OFF   (HS_OFF + HS_SZ)
#define GS_SZ    (BR * G_DIM)             // 7168 floats
#define XS_OFF   (GS_OFF + GS_SZ)
#define XS_SZ    (T_LEN * BR * 2)         // 11200 floats
#define SMEM_FLOATS (XS_OFF + XS_SZ)
#define SMEM_BYTES  (SMEM_FLOATS * 4)

__device__ __forceinline__ unsigned long long pack2(float a, float b) {
    unsigned long long r;
    asm("mov.b64 %0, {%1, %2};" : "=l"(r) : "f"(a), "f"(b));
    return r;
}
__device__ __forceinline__ void unpack2(unsigned long long v, float& a, float& b) {
    asm("mov.b64 {%0, %1}, %2;" : "=f"(a), "=f"(b) : "l"(v));
}
__device__ __forceinline__ unsigned long long fma2(unsigned long long a,
                                                   unsigned long long b,
                                                   unsigned long long c) {
    unsigned long long d;
    asm("fma.rn.f32x2 %0, %1, %2, %3;" : "=l"(d) : "l"(a), "l"(b), "l"(c));
    return d;
}
__device__ __forceinline__ unsigned long long add2(unsigned long long a,
                                                   unsigned long long b) {
    unsigned long long d;
    asm("add.rn.f32x2 %0, %1, %2;" : "=l"(d) : "l"(a), "l"(b));
    return d;
}

__device__ __forceinline__ float ex2f(float x) {
    float r; asm("ex2.approx.f32 %0, %1;" : "=f"(r) : "f"(x)); return r;
}
__device__ __forceinline__ float rcpf(float x) {
    float r; asm("rcp.approx.f32 %0, %1;" : "=f"(r) : "f"(x)); return r;
}
__device__ __forceinline__ float sigf(float x) {
    float e = ex2f(-1.4426950408889634f * x);
    return rcpf(1.0f + e);
}
__device__ __forceinline__ float tanhf_(float x) {
    float e = ex2f(-2.8853900817779268f * x);
    return fmaf(2.0f, rcpf(1.0f + e), -1.0f);
}

__global__ __launch_bounds__(NTHR, 1)
void lstm_kernel(const float* __restrict__ x,
                 const float* __restrict__ W_ih,
                 const float* __restrict__ W_hh,
                 const float* __restrict__ b_ih,
                 const float* __restrict__ b_hh,
                 const float* __restrict__ W_fc,
                 const float* __restrict__ b_fc,
                 float* __restrict__ out) {
    extern __shared__ float sm[];
    float*  hsm = sm + HS_OFF;            // [28][64]
    float*  gsm = sm + GS_OFF;            // [28][256]
    float2* xsf = (float2*)(sm + XS_OFF); // [200][28]

    const int tid = threadIdx.x;
    const int gp  = tid & 127;            // gate pair 0..127
    const int s   = tid >> 7;             // batch half 0/1
    const int g0  = 2 * gp;
    const int g1  = 2 * gp + 1;
    const int bs  = s * HROWS;            // this half's first row
    const int base = blockIdx.x * BR;

    // ---- weights for 2 gate rows, k-packed f32x2 (128 regs) ----
    unsigned long long w0[H_DIM / 2], w1[H_DIM / 2];
    {
        const float2* wr0 = (const float2*)(W_hh + g0 * H_DIM);
        const float2* wr1 = (const float2*)(W_hh + g1 * H_DIM);
        #pragma unroll
        for (int m = 0; m < H_DIM / 2; m++) {
            float2 a = wr0[m]; w0[m] = pack2(a.x, a.y);
            float2 b = wr1[m]; w1[m] = pack2(b.x, b.y);
        }
    }
    const float wA0 = W_ih[g0 * 2 + 0], wA1 = W_ih[g0 * 2 + 1];
    const float wB0 = W_ih[g1 * 2 + 0], wB1 = W_ih[g1 * 2 + 1];
    const float bias0 = b_ih[g0] + b_hh[g0];
    const float bias1 = b_ih[g1] + b_hh[g1];
    const float bfc = b_fc[0];

    // ---- zero h state ----
    for (int i = tid; i < HS_SZ; i += NTHR) hsm[i] = 0.0f;

    // ---- stage x: [t][b] -> float2(x0,x1) ----
    for (int id = tid; id < T_LEN * BR; id += NTHR) {
        int t = id / BR;
        int b = id - t * BR;
        int gb = base + b;
        float2 v = make_float2(0.0f, 0.0f);
        if (gb < B_TOT) v = *(const float2*)(x + gb * (T_LEN * 2) + 2 * t);
        xsf[t * BR + b] = v;
    }

    float c_state[7];
    #pragma unroll
    for (int r = 0; r < 7; r++) c_state[r] = 0.0f;

    __syncthreads();

    // ph1 body for this thread's 14 rows at time t (dense FMA stream)
    auto ph1 = [&](int t) {
        const float2* xrow = xsf + t * BR;
        #pragma unroll
        for (int bb = 0; bb < HROWS; bb++) {
            const int b = bs + bb;
            const ulonglong2* hr = (const ulonglong2*)(hsm + b * H_DIM);
            unsigned long long a0a = pack2(0.0f, 0.0f);
            unsigned long long a0b = a0a, a1a = a0a, a1b = a0a;
            #pragma unroll
            for (int m = 0; m < H_DIM / 4; m++) {
                ulonglong2 hv = hr[m];
                a0a = fma2(hv.x, w0[2 * m + 0], a0a);
                a0b = fma2(hv.y, w0[2 * m + 1], a0b);
                a1a = fma2(hv.x, w1[2 * m + 0], a1a);
                a1b = fma2(hv.y, w1[2 * m + 1], a1b);
            }
            float2 xv = xrow[b];
            float l0, h0, l1, h1;
            unpack2(add2(a0a, a0b), l0, h0);
            unpack2(add2(a1a, a1b), l1, h1);
            float gv0 = bias0 + wA0 * xv.x + wA1 * xv.y + (l0 + h0);
            float gv1 = bias1 + wB0 * xv.x + wB1 * xv.y + (l1 + h1);
            *(float2*)(gsm + b * G_DIM + g0) = make_float2(gv0, gv1);
        }
    };

    // ph2 body: this thread's 7 (b,j) items within its OWN half (dense)
    auto ph2 = [&]() {
        #pragma unroll
        for (int it = 0; it < 7; it++) {
            int idx = gp + 128 * it;          // 0..895
            int b = bs + (idx >> 6);
            int j = idx & 63;
            const float* gr = gsm + b * G_DIM + j;
            float gi = gr[0];
            float gf = gr[64];
            float gg = gr[128];
            float go = gr[192];
            float i_ = sigf(gi);
            float f_ = sigf(gf);
            float g_ = tanhf_(gg);
            float o_ = sigf(go);
            float c = f_ * c_state[it] + i_ * g_;
            c_state[it] = c;
            hsm[b * H_DIM + j] = o_ * tanhf_(c);
        }
    };

    for (int t = 0; t < T_LEN; t++) {
        // interval 1: s0 -> ph1(A,t);  s1 -> ph2(B, t-1)
        if (s == 0)      ph1(t);
        else if (t > 0)  ph2();
        __syncthreads();
        // interval 2: s1 -> ph1(B,t);  s0 -> ph2(A, t)
        if (s == 1)      ph1(t);
        else             ph2();
        __syncthreads();
    }
    if (s == 1) ph2();   // ph2(B, 199)
    __syncthreads();

    // ---- final projection: out[b] = dot(h_last, W_fc) + b_fc ----
    if (tid < H_DIM) sm[XS_OFF + tid] = W_fc[tid];  // xs no longer needed
    __syncthreads();
    if (tid < BR) {
        int gb = base + tid;
        if (gb < B_TOT) {
            float acc = 0.0f;
            #pragma unroll
            for (int jj = 0; jj < H_DIM; jj++)
                acc += hsm[tid * H_DIM + jj] * sm[XS_OFF + jj];
            out[gb] = acc + bfc;
        }
    }
}

extern "C" void kernel_launch(void* const* d_in, const int* in_sizes, int n_in,
                              void* d_out, int out_size) {
    const float* x    = (const float*)d_in[0];
    const float* W_ih = (const float*)d_in[1];
    const float* W_hh = (const float*)d_in[2];
    const float* b_ih = (const float*)d_in[3];
    const float* b_hh = (const float*)d_in[4];
    const float* W_fc = (const float*)d_in[5];
    const float* b_fc = (const float*)d_in[6];
    float* out = (float*)d_out;

    cudaFuncSetAttribute(lstm_kernel,
                         cudaFuncAttributeMaxDynamicSharedMemorySize,
                         SMEM_BYTES);

    int grid = (B_TOT + BR - 1) / BR;  // 147
    lstm_kernel<<<grid, NTHR, SMEM_BYTES>>>(x, W_ih, W_hh, b_ih, b_hh,
                                            W_fc, b_fc, out);
}

// round 17
// speedup vs baseline: 1.2991x; 1.2488x over previous
#include <cuda_runtime.h>
#include <cuda_bf16.h>

// LSTM: B=4096, T=200, IN=2, H=64, gates=256 (i,f,g,o torch order)
//
// R16 design. History:
//  R3 (955us): L1-bound (AI = 2 FFMA2/LDS.128).
//  R4 (754us): AI doubled -> fma 54.7% = FMA floor; ph2+barriers serial.
//  R10 (990us REGRESS): shfl/divergent ph2 poisoned dense bodies.
//  R12 (951us REGRESS): intra-CTA stagger left 1 ph1 warp/SMSP -> exposed
//       LDS latency + reg spills. Lesson: overlap must come from
//       INDEPENDENT CTAs, not coupled warps.
// R16: exact R4 per-thread work, but CTA split in half: 128 threads,
// BR=14, grid=293, 2 CTAs/SM (regs ~190*128*2 = 49K < 64K; smem 40KB*2).
// Each SMSP gets 2 full ph1 warps from different CTAs with independent
// barriers -> ph2/convoy of one CTA hides under the other's FMA stream.

#define B_TOT   4096
#define T_LEN   200
#define H_DIM   64
#define G_DIM   256           // 4*H
#define BR      14            // batch rows per CTA
#define NTHR    128

// smem float offsets: hsm | gsm | xs
#define HS_OFF   0
#define HS_SZ    (BR * H_DIM)             // 896 floats
#define GS_OFF   (HS_OFF + HS_SZ)
#define GS_SZ    (BR * G_DIM)             // 3584 floats
#define XS_OFF   (GS_OFF + GS_SZ)
#define XS_SZ    (T_LEN * BR * 2)         // 5600 floats
#define SMEM_FLOATS (XS_OFF + XS_SZ)      // 10080
#define SMEM_BYTES  (SMEM_FLOATS * 4)     // 40320 B

__device__ __forceinline__ unsigned long long pack2(float a, float b) {
    unsigned long long r;
    asm("mov.b64 %0, {%1, %2};" : "=l"(r) : "f"(a), "f"(b));
    return r;
}
__device__ __forceinline__ void unpack2(unsigned long long v, float& a, float& b) {
    asm("mov.b64 {%0, %1}, %2;" : "=f"(a), "=f"(b) : "l"(v));
}
__device__ __forceinline__ unsigned long long fma2(unsigned long long a,
                                                   unsigned long long b,
                                                   unsigned long long c) {
    unsigned long long d;
    asm("fma.rn.f32x2 %0, %1, %2, %3;" : "=l"(d) : "l"(a), "l"(b), "l"(c));
    return d;
}
__device__ __forceinline__ unsigned long long add2(unsigned long long a,
                                                   unsigned long long b) {
    unsigned long long d;
    asm("add.rn.f32x2 %0, %1, %2;" : "=l"(d) : "l"(a), "l"(b));
    return d;
}

__device__ __forceinline__ float ex2f(float x) {
    float r; asm("ex2.approx.f32 %0, %1;" : "=f"(r) : "f"(x)); return r;
}
__device__ __forceinline__ float rcpf(float x) {
    float r; asm("rcp.approx.f32 %0, %1;" : "=f"(r) : "f"(x)); return r;
}
__device__ __forceinline__ float sigf(float x) {
    float e = ex2f(-1.4426950408889634f * x);
    return rcpf(1.0f + e);
}
__device__ __forceinline__ float tanhf_(float x) {
    float e = ex2f(-2.8853900817779268f * x);
    return fmaf(2.0f, rcpf(1.0f + e), -1.0f);
}

__global__ __launch_bounds__(NTHR, 2)
void lstm_kernel(const float* __restrict__ x,
                 const float* __restrict__ W_ih,
                 const float* __restrict__ W_hh,
                 const float* __restrict__ b_ih,
                 const float* __restrict__ b_hh,
                 const float* __restrict__ W_fc,
                 const float* __restrict__ b_fc,
                 float* __restrict__ out) {
    extern __shared__ float sm[];
    float*  hsm = sm + HS_OFF;            // [14][64]
    float*  gsm = sm + GS_OFF;            // [14][256]
    float2* xsf = (float2*)(sm + XS_OFF); // [200][14]

    const int tid = threadIdx.x;          // 0..127 = gate pair index
    const int g0  = 2 * tid;
    const int g1  = 2 * tid + 1;
    const int base = blockIdx.x * BR;

    // ---- weights for 2 gate rows, k-packed f32x2 (128 regs) ----
    unsigned long long w0[H_DIM / 2], w1[H_DIM / 2];
    {
        const float2* wr0 = (const float2*)(W_hh + g0 * H_DIM);
        const float2* wr1 = (const float2*)(W_hh + g1 * H_DIM);
        #pragma unroll
        for (int m = 0; m < H_DIM / 2; m++) {
            float2 a = wr0[m]; w0[m] = pack2(a.x, a.y);
            float2 b = wr1[m]; w1[m] = pack2(b.x, b.y);
        }
    }
    const float wA0 = W_ih[g0 * 2 + 0], wA1 = W_ih[g0 * 2 + 1];
    const float wB0 = W_ih[g1 * 2 + 0], wB1 = W_ih[g1 * 2 + 1];
    const float bias0 = b_ih[g0] + b_hh[g0];
    const float bias1 = b_ih[g1] + b_hh[g1];
    const float bfc = b_fc[0];

    // ---- zero h state ----
    for (int i = tid; i < HS_SZ; i += NTHR) hsm[i] = 0.0f;

    // ---- stage x: [t][b] -> float2(x0,x1) ----
    for (int id = tid; id < T_LEN * BR; id += NTHR) {
        int t = id / BR;
        int b = id - t * BR;
        int gb = base + b;
        float2 v = make_float2(0.0f, 0.0f);
        if (gb < B_TOT) v = *(const float2*)(x + gb * (T_LEN * 2) + 2 * t);
        xsf[t * BR + b] = v;
    }

    float c_state[7];
    #pragma unroll
    for (int r = 0; r < 7; r++) c_state[r] = 0.0f;

    __syncthreads();

    for (int t = 0; t < T_LEN; t++) {
        const float2* xrow = xsf + t * BR;

        // ---- phase 1: 2 gates x 14 batch rows per thread ----
        #pragma unroll
        for (int b = 0; b < BR; b++) {
            const ulonglong2* hr = (const ulonglong2*)(hsm + b * H_DIM);
            unsigned long long a0a = pack2(0.0f, 0.0f);
            unsigned long long a0b = a0a, a1a = a0a, a1b = a0a;
            #pragma unroll
            for (int m = 0; m < H_DIM / 4; m++) {
                ulonglong2 hv = hr[m];  // h[4m..4m+3] as two f32x2
                a0a = fma2(hv.x, w0[2 * m + 0], a0a);
                a0b = fma2(hv.y, w0[2 * m + 1], a0b);
                a1a = fma2(hv.x, w1[2 * m + 0], a1a);
                a1b = fma2(hv.y, w1[2 * m + 1], a1b);
            }
            float2 xv = xrow[b];
            float l0, h0, l1, h1;
            unpack2(add2(a0a, a0b), l0, h0);
            unpack2(add2(a1a, a1b), l1, h1);
            float gv0 = bias0 + wA0 * xv.x + wA1 * xv.y + (l0 + h0);
            float gv1 = bias1 + wB0 * xv.x + wB1 * xv.y + (l1 + h1);
            *(float2*)(gsm + b * G_DIM + g0) = make_float2(gv0, gv1);
        }
        __syncthreads();

        // ---- phase 2: activations / state update, 7 (b,j) per thread ----
        #pragma unroll
        for (int it = 0; it < 7; it++) {
            int idx = tid + NTHR * it;        // 0..895
            int b = idx >> 6;                 // 0..13
            int j = idx & 63;
            const float* gr = gsm + b * G_DIM + j;
            float gi = gr[0];
            float gf = gr[64];
            float gg = gr[128];
            float go = gr[192];
            float i_ = sigf(gi);
            float f_ = sigf(gf);
            float g_ = tanhf_(gg);
            float o_ = sigf(go);
            float c = f_ * c_state[it] + i_ * g_;
            c_state[it] = c;
            hsm[b * H_DIM + j] = o_ * tanhf_(c);
        }
        __syncthreads();
    }

    // ---- final projection: out[b] = dot(h_last, W_fc) + b_fc ----
    if (tid < H_DIM) sm[XS_OFF + tid] = W_fc[tid];  // xs no longer needed
    __syncthreads();
    if (tid < BR) {
        int gb = base + tid;
        if (gb < B_TOT) {
            float acc = 0.0f;
            #pragma unroll
            for (int jj = 0; jj < H_DIM; jj++)
                acc += hsm[tid * H_DIM + jj] * sm[XS_OFF + jj];
            out[gb] = acc + bfc;
        }
    }
}

extern "C" void kernel_launch(void* const* d_in, const int* in_sizes, int n_in,
                              void* d_out, int out_size) {
    const float* x    = (const float*)d_in[0];
    const float* W_ih = (const float*)d_in[1];
    const float* W_hh = (const float*)d_in[2];
    const float* b_ih = (const float*)d_in[3];
    const float* b_hh = (const float*)d_in[4];
    const float* W_fc = (const float*)d_in[5];
    const float* b_fc = (const float*)d_in[6];
    float* out = (float*)d_out;

    cudaFuncSetAttribute(lstm_kernel,
                         cudaFuncAttributeMaxDynamicSharedMemorySize,
                         SMEM_BYTES);

    int grid = (B_TOT + BR - 1) / BR;  // 293
    lstm_kernel<<<grid, NTHR, SMEM_BYTES>>>(x, W_ih, W_hh, b_ih, b_hh,
                                            W_fc, b_fc, out);
}